// round 15
// baseline (speedup 1.0000x reference)
#include <cuda_runtime.h>
#include <math.h>
#include <stdint.h>

#define C 16
#define D 512
#define CHUNK_ROWS 256
#define DPT 128            // float2-dim slots per block (256 dims per half)
#define NPAIRS (C*(C-1)/2)
#define NCHUNK 256         // row chunks (N=65536 / 256)
#define PBLK (NCHUNK*2)    // pass-1 partial blocks = 512 (2 dim-halves)
#define GRPS 8             // stage-A groups
#define CPG (NCHUNK/GRPS)  // chunks per group = 32

// ---------------- device scratch (no allocations allowed) ----------------
__device__ float4 g_partial4[PBLK * C * DPT];    // 16 MB (s0,q0,s1,q1)
__device__ float2 g_pA[GRPS * C * D];            // 512 KB (L2-resident)
__device__ int    g_order[NCHUNK * CHUNK_ROWS];  // sorted (row | class<<16)
__device__ int    g_choff[NCHUNK * 17];          // per-chunk class offsets
__device__ int    g_chunkhist[NCHUNK * C];       // per-chunk class histogram
__device__ int    g_counts[C];
__device__ double g_pairsum[NPAIRS];

__device__ __forceinline__ int get_id(const int* ids32, int i, int is64) {
    return is64 ? ids32[2 * i] : ids32[i];    // little-endian low word
}

__device__ __forceinline__ int detect_is64(const int* ids32, int n) {
    int lim = n / 2; if (lim > 64) lim = 64;
    int any = 0;
    for (int i = 0; i < lim; i++) any |= ids32[2 * i + 1];
    return any == 0;
}

// ---------------- launch 1: per-chunk class-sorted order (deterministic) ---
__global__ __launch_bounds__(256) void k_order(const int* __restrict__ ids32,
                                               int n) {
    __shared__ int s_whist[8][C];
    __shared__ int s_wbase[8][C];
    __shared__ int s_hist[C];
    __shared__ int s_off[17];
    __shared__ int s_is64;
    int t = threadIdx.x;
    int w = t >> 5, lane = t & 31;
    int chunk = blockIdx.x;

    if (t < 8 * C) ((int*)s_whist)[t] = 0;
    if (t == 0) s_is64 = detect_is64(ids32, n);
    __syncthreads();
    int c = get_id(ids32, chunk * CHUNK_ROWS + t, s_is64) & (C - 1);

    unsigned mask = __match_any_sync(0xffffffffu, c);
    int lr = __popc(mask & ((1u << lane) - 1u));
    if (lr == 0) s_whist[w][c] = __popc(mask);
    __syncthreads();

    if (t < C) {
        int acc = 0;
#pragma unroll
        for (int ww = 0; ww < 8; ww++) { s_wbase[ww][t] = acc; acc += s_whist[ww][t]; }
        s_hist[t] = acc;
    }
    __syncthreads();
    if (t == 0) {
        int acc = 0;
#pragma unroll
        for (int cc = 0; cc < C; cc++) { s_off[cc] = acc; acc += s_hist[cc]; }
        s_off[C] = acc;
    }
    __syncthreads();

    int pos = s_off[c] + s_wbase[w][c] + lr;
    g_order[chunk * CHUNK_ROWS + pos] = t | (c << 16);
    if (t < 17) g_choff[chunk * 17 + t] = s_off[t];
    if (t < C)  g_chunkhist[chunk * C + t] = s_hist[t];
}

// ---------------- launch 2: pass 1 (float2 streaming) + counts (block 0) ---
// block = (chunk of 256 rows) x (half of 512 dims), 128 threads, thread t
// owns dims (half*256 + 2t, +1). Register accumulate, flush on class change.
#define P1STEP(pp, vv)                                              \
    {                                                               \
        int cc = (pp) >> 16;                                        \
        if (cc != cur) {                                            \
            out[cur * DPT] = make_float4(s0, q0, s1, q1);           \
            s0 = q0 = s1 = q1 = 0.f; cur = cc;                      \
        }                                                           \
        s0 += (vv).x; q0 = fmaf((vv).x, (vv).x, q0);                \
        s1 += (vv).y; q1 = fmaf((vv).y, (vv).y, q1);                \
    }

__global__ __launch_bounds__(128) void k_pass1(const float* __restrict__ hidden) {
    __shared__ int s_off[17];
    __shared__ int s_cnt[128];
    int t = threadIdx.x;

    // block 0: reduce chunk histograms -> g_counts (8 segments x 16 classes)
    if (blockIdx.x == 0) {
        int c = t & 15, seg = t >> 4;            // seg 0..7
        int acc = 0;
        for (int ch = seg; ch < NCHUNK; ch += 8) acc += g_chunkhist[ch * C + c];
        s_cnt[t] = acc;
        __syncthreads();
        if (t < C) {
            int tot = 0;
#pragma unroll
            for (int s2 = 0; s2 < 8; s2++) tot += s_cnt[s2 * 16 + t];
            g_counts[t] = tot;
        }
        __syncthreads();
    }

    int half  = blockIdx.x & 1;
    int chunk = blockIdx.x >> 1;
    if (t < 17) s_off[t] = g_choff[chunk * 17 + t];
    __syncthreads();

    const float2* base = reinterpret_cast<const float2*>(hidden)
                       + (size_t)chunk * CHUNK_ROWS * 256 + half * DPT + t;
    const int*    ord  = g_order + chunk * CHUNK_ROWS;
    float4*       out  = g_partial4 + (size_t)blockIdx.x * (C * DPT) + t;

    float s0 = 0.f, q0 = 0.f, s1 = 0.f, q1 = 0.f;
    int cur = ord[0] >> 16;
#pragma unroll 1
    for (int k = 0; k < CHUNK_ROWS; k += 8) {
        int p0 = ord[k + 0], p1 = ord[k + 1], p2 = ord[k + 2], p3 = ord[k + 3];
        int p4 = ord[k + 4], p5 = ord[k + 5], p6 = ord[k + 6], p7 = ord[k + 7];
        float2 v0 = base[(size_t)(p0 & 0xffff) * 256];
        float2 v1 = base[(size_t)(p1 & 0xffff) * 256];
        float2 v2 = base[(size_t)(p2 & 0xffff) * 256];
        float2 v3 = base[(size_t)(p3 & 0xffff) * 256];
        float2 v4 = base[(size_t)(p4 & 0xffff) * 256];
        float2 v5 = base[(size_t)(p5 & 0xffff) * 256];
        float2 v6 = base[(size_t)(p6 & 0xffff) * 256];
        float2 v7 = base[(size_t)(p7 & 0xffff) * 256];
        P1STEP(p0, v0) P1STEP(p1, v1) P1STEP(p2, v2) P1STEP(p3, v3)
        P1STEP(p4, v4) P1STEP(p5, v5) P1STEP(p6, v6) P1STEP(p7, v7)
    }
    out[cur * DPT] = make_float4(s0, q0, s1, q1);
#pragma unroll
    for (int cc = 0; cc < C; cc++)
        if (s_off[cc + 1] == s_off[cc])
            out[cc * DPT] = make_float4(0.f, 0.f, 0.f, 0.f);
}

// ---------------- launch 3: pass 2 stage A (wide coalesced, float4) --------
// thread -> (grp, c, half, tslot); sums 32 chunks; writes float4 (2 dims).
__global__ __launch_bounds__(256) void k_pass2a() {
    int gid = blockIdx.x * 256 + threadIdx.x;      // 0 .. 32767
    int grp = gid >> 12;                           // 0 .. 7
    int r   = gid & 4095;                          // c*256 + half*128 + t
    int c   = r >> 8;
    int hh  = (r >> 7) & 1;
    int t   = r & 127;
    const float4* p = g_partial4 + (size_t)c * DPT + t;
    float s0 = 0.f, q0 = 0.f, s1 = 0.f, q1 = 0.f;
#pragma unroll 8
    for (int k = 0; k < CPG; k++) {
        int chunk = grp * CPG + k;                 // 0 .. 255
        int blk   = (chunk << 1) | hh;             // 0 .. 511
        float4 v = p[(size_t)blk * (C * DPT)];
        s0 += v.x; q0 += v.y; s1 += v.z; q1 += v.w;
    }
    int dim = hh * 256 + 2 * t;                    // even
    reinterpret_cast<float4*>(g_pA)[(grp * (C * D) + c * D + dim) >> 1] =
        make_float4(s0, q0, s1, q1);
}

// ---------------- launch 4 (profiled): pair kernel --------------------------
// fp32 stats from 512 KB L2-resident g_pA; hybrid bitonic sort (register +
// shfl for jj<32, smem for jj>=32 -> 10 cross-warp phases instead of 45);
// large-b asymptotic log-betainc on top-K; block sum.
__global__ __launch_bounds__(D) void k_pairs(const int* __restrict__ dptr) {
    __shared__ float sx[D];
    __shared__ float sred[D];
    int t = threadIdx.x;

    int bid = blockIdx.x;
    int i = 0, rem = bid;
    while (rem >= C - 1 - i) { rem -= C - 1 - i; i++; }
    int j = i + 1 + rem;

    float ni = (float)g_counts[i], nj = (float)g_counts[j];
    float pc = ni + nj;
    float d2 = pc - 2.f;
    if (d2 == 0.f) d2 = 1e-5f;
    float b = d2 * 0.5f;

    float sxi = 0.f, qqi = 0.f, sxj = 0.f, qqj = 0.f;
#pragma unroll
    for (int g = 0; g < GRPS; g++) {
        float2 vi = g_pA[g * (C * D) + i * D + t];
        float2 vj = g_pA[g * (C * D) + j * D + t];
        sxi += vi.x; qqi += vi.y;
        sxj += vj.x; qqj += vj.y;
    }
    float mi = sxi / ni;
    float wi = qqi - sxi * mi;
    float mj = sxj / nj;
    float wj = qqj - sxj * mj;

    float hd   = (mi - mj) * 0.5f;
    float betw = hd * hd * pc;
    float x = betw / (betw + wi + wj);
    x = fminf(fmaxf(x, 1e-37f), 1.f - 1e-5f);

    // hybrid bitonic sort, descending; thread t ends holding sorted[t]
    float v = x;
#pragma unroll
    for (int k = 2; k <= D; k <<= 1) {
#pragma unroll
        for (int jj = k >> 1; jj > 0; jj >>= 1) {
            bool keepMax = (((t & k) == 0) == ((t & jj) == 0));
            float pv;
            if (jj >= 32) {
                sx[t] = v;
                __syncthreads();
                pv = sx[t ^ jj];
                __syncthreads();
            } else {
                pv = __shfl_xor_sync(0xffffffffu, v, jj);
            }
            v = keepMax ? fmaxf(v, pv) : fminf(v, pv);
        }
    }

    int K = 64;
    if (dptr) {
        int kv = dptr[0];
        if (kv >= 1 && kv <= D) K = kv;
    }

    float val = 0.f;
    if (t < K) {
        float s2 = -b * log1pf(-v);                // s = -b ln(1-x)
        float rs = sqrtf(s2);
        const float inv_sqrtpi = 0.5641895835477563f;  // 1/sqrt(pi)
        float I = erff(rs) - rs * expf(-s2) * (inv_sqrtpi * 0.25f / b);
        I = fminf(fmaxf(I, 1e-38f), 1.f);
        val = logf(I);
    }
    sred[t] = val;
    __syncthreads();
    for (int s = D / 2; s > 0; s >>= 1) {
        if (t < s) sred[t] += sred[t + s];
        __syncthreads();
    }
    if (t == 0) g_pairsum[bid] = (double)sred[0];
}

// ---------------- launch 5: final scalar reduce -----------------------------
__global__ void k_final(float* out) {
    __shared__ double sr[128];
    int t = threadIdx.x;
    sr[t] = (t < NPAIRS) ? g_pairsum[t] : 0.0;
    __syncthreads();
    for (int s = 64; s > 0; s >>= 1) {
        if (t < s) sr[t] += sr[t + s];
        __syncthreads();
    }
    if (t == 0) out[0] = (float)(-sr[0]);
}

// ---------------- launch ----------------
extern "C" void kernel_launch(void* const* d_in, const int* in_sizes, int n_in,
                              void* d_out, int out_size) {
    const float* hidden = (const float*)d_in[0];
    const int*   ids32  = (const int*)d_in[1];
    const int*   dptr   = (n_in > 2) ? (const int*)d_in[2] : nullptr;

    int N = in_sizes[0] / D;            // 65536

    k_order <<<NCHUNK, 256>>>(ids32, N);                 // launch 1
    k_pass1 <<<PBLK, 128>>>(hidden);                     // launch 2
    k_pass2a<<<(GRPS * C * D / 2) / 256, 256>>>();       // launch 3 (128 blocks)
    k_pairs <<<NPAIRS, D>>>(dptr);                       // launch 4 (profiled)
    k_final <<<1, 128>>>((float*)d_out);                 // launch 5
}

// round 16
// speedup vs baseline: 1.2827x; 1.2827x over previous
#include <cuda_runtime.h>
#include <math.h>
#include <stdint.h>

#define C 16
#define D 512
#define CHUNK_ROWS 256
#define DPQ 128            // dims per quarter-block in pass 1
#define NPAIRS (C*(C-1)/2)
#define NCHUNK 256         // row chunks (N=65536 / 256)
#define PBLK (NCHUNK*4)    // pass-1 partial blocks = 1024 (4 dim-quarters)
#define GRPS 8             // stage-A groups
#define CPG (NCHUNK/GRPS)  // chunks per group = 32

// ---------------- device scratch (no allocations allowed) ----------------
__device__ float2 g_partial[PBLK * C * DPQ];     // 16 MB
__device__ float2 g_pA[GRPS * C * D];            // 512 KB (L2-resident)
__device__ int    g_order[NCHUNK * CHUNK_ROWS];  // sorted (row | class<<16)
__device__ int    g_choff[NCHUNK * 17];          // per-chunk class offsets
__device__ int    g_chunkhist[NCHUNK * C];       // per-chunk class histogram
__device__ int    g_counts[C];
__device__ double g_pairsum[NPAIRS];

__device__ __forceinline__ int get_id(const int* ids32, int i, int is64) {
    return is64 ? ids32[2 * i] : ids32[i];    // little-endian low word
}

__device__ __forceinline__ int detect_is64(const int* ids32, int n) {
    int lim = n / 2; if (lim > 64) lim = 64;
    int any = 0;
    for (int i = 0; i < lim; i++) any |= ids32[2 * i + 1];
    return any == 0;
}

// ---------------- launch 1: per-chunk class-sorted order (deterministic) ---
__global__ __launch_bounds__(256) void k_order(const int* __restrict__ ids32,
                                               int n) {
    __shared__ int s_whist[8][C];
    __shared__ int s_wbase[8][C];
    __shared__ int s_hist[C];
    __shared__ int s_off[17];
    __shared__ int s_is64;
    int t = threadIdx.x;
    int w = t >> 5, lane = t & 31;
    int chunk = blockIdx.x;

    if (t < 8 * C) ((int*)s_whist)[t] = 0;
    if (t == 0) s_is64 = detect_is64(ids32, n);
    __syncthreads();
    int c = get_id(ids32, chunk * CHUNK_ROWS + t, s_is64) & (C - 1);

    unsigned mask = __match_any_sync(0xffffffffu, c);
    int lr = __popc(mask & ((1u << lane) - 1u));
    if (lr == 0) s_whist[w][c] = __popc(mask);
    __syncthreads();

    if (t < C) {
        int acc = 0;
#pragma unroll
        for (int ww = 0; ww < 8; ww++) { s_wbase[ww][t] = acc; acc += s_whist[ww][t]; }
        s_hist[t] = acc;
    }
    __syncthreads();
    if (t == 0) {
        int acc = 0;
#pragma unroll
        for (int cc = 0; cc < C; cc++) { s_off[cc] = acc; acc += s_hist[cc]; }
        s_off[C] = acc;
    }
    __syncthreads();

    int pos = s_off[c] + s_wbase[w][c] + lr;
    g_order[chunk * CHUNK_ROWS + pos] = t | (c << 16);
    if (t < 17) g_choff[chunk * 17 + t] = s_off[t];
    if (t < C)  g_chunkhist[chunk * C + t] = s_hist[t];
}

// ---------------- launch 2: pass 1 (R14 geometry) + counts (block 0) -------
// block = (chunk of 256 rows) x (quarter of the 512 dims), 128 threads.
// 1024 blocks -> ~7 blocks/SM, ~28 warps/SM. Register accumulate, flush on
// class change (block-uniform branch), 8-wide batched scalar loads.
#define P1STEP(pp, vv)                                              \
    {                                                               \
        int cc = (pp) >> 16;                                        \
        if (cc != cur) {                                            \
            out[cur * DPQ] = make_float2(s, q);                     \
            s = 0.f; q = 0.f; cur = cc;                             \
        }                                                           \
        s += (vv); q = fmaf((vv), (vv), q);                         \
    }

__global__ __launch_bounds__(128) void k_pass1(const float* __restrict__ hidden) {
    __shared__ int s_off[17];
    __shared__ int s_cnt[128];
    int t = threadIdx.x;

    // block 0: reduce chunk histograms -> g_counts (8 segments x 16 classes)
    if (blockIdx.x == 0) {
        int c = t & 15, seg = t >> 4;            // seg 0..7
        int acc = 0;
        for (int ch = seg; ch < NCHUNK; ch += 8) acc += g_chunkhist[ch * C + c];
        s_cnt[t] = acc;
        __syncthreads();
        if (t < C) {
            int tot = 0;
#pragma unroll
            for (int s2 = 0; s2 < 8; s2++) tot += s_cnt[s2 * 16 + t];
            g_counts[t] = tot;
        }
        __syncthreads();
    }

    int quarter = blockIdx.x & 3;
    int chunk   = blockIdx.x >> 2;
    if (t < 17) s_off[t] = g_choff[chunk * 17 + t];
    __syncthreads();

    const float* base = hidden + (size_t)chunk * CHUNK_ROWS * D + quarter * DPQ + t;
    const int*   ord  = g_order + chunk * CHUNK_ROWS;
    float2*      out  = g_partial + (size_t)blockIdx.x * (C * DPQ) + t;

    float s = 0.f, q = 0.f;
    int cur = ord[0] >> 16;
#pragma unroll 1
    for (int k = 0; k < CHUNK_ROWS; k += 8) {
        int p0 = ord[k + 0], p1 = ord[k + 1], p2 = ord[k + 2], p3 = ord[k + 3];
        int p4 = ord[k + 4], p5 = ord[k + 5], p6 = ord[k + 6], p7 = ord[k + 7];
        float v0 = base[(size_t)(p0 & 0xffff) * D];
        float v1 = base[(size_t)(p1 & 0xffff) * D];
        float v2 = base[(size_t)(p2 & 0xffff) * D];
        float v3 = base[(size_t)(p3 & 0xffff) * D];
        float v4 = base[(size_t)(p4 & 0xffff) * D];
        float v5 = base[(size_t)(p5 & 0xffff) * D];
        float v6 = base[(size_t)(p6 & 0xffff) * D];
        float v7 = base[(size_t)(p7 & 0xffff) * D];
        P1STEP(p0, v0) P1STEP(p1, v1) P1STEP(p2, v2) P1STEP(p3, v3)
        P1STEP(p4, v4) P1STEP(p5, v5) P1STEP(p6, v6) P1STEP(p7, v7)
    }
    out[cur * DPQ] = make_float2(s, q);
#pragma unroll
    for (int cc = 0; cc < C; cc++)
        if (s_off[cc + 1] == s_off[cc]) out[cc * DPQ] = make_float2(0.f, 0.f);
}

// ---------------- launch 3: pass 2 stage A (wide coalesced) ----------------
// item = c*512 + dim (8192 items). 8 groups x 32 chunks each; blk = chunk*4+q.
__global__ __launch_bounds__(256) void k_pass2a() {
    int gid  = blockIdx.x * 256 + threadIdx.x;     // 0 .. 65535
    int item = gid & (C * D - 1);                  // 0 .. 8191
    int grp  = gid >> 13;                          // 0 .. 7
    int c    = item >> 9;
    int dim  = item & (D - 1);
    int quarter = dim >> 7;
    int tq      = dim & (DPQ - 1);
    const float2* p = g_partial + (size_t)c * DPQ + tq;
    float sx = 0.f, qq = 0.f;
#pragma unroll 8
    for (int k = 0; k < CPG; k++) {
        int chunk = grp * CPG + k;                 // 0 .. 255
        int blk   = (chunk << 2) | quarter;        // 0 .. 1023
        float2 v = p[(size_t)blk * (C * DPQ)];
        sx += v.x; qq += v.y;
    }
    g_pA[grp * (C * D) + item] = make_float2(sx, qq);
}

// ---------------- launch 4 (profiled): pair kernel --------------------------
// fp32 stats from 512 KB L2-resident g_pA; hybrid bitonic sort (register +
// shfl for jj<32, smem for jj>=32 -> 10 cross-warp phases instead of 45);
// large-b asymptotic log-betainc on top-K; block sum.
// I_x(1/2,b) = erf(sqrt(s)) - sqrt(s)e^{-s}/(4b sqrt(pi)) + O(1/b^2),
// s = -b*log1p(-x). Monotone in x, so top-k commutes with the transform.
__global__ __launch_bounds__(D) void k_pairs(const int* __restrict__ dptr) {
    __shared__ float sx[D];
    __shared__ float sred[D];
    int t = threadIdx.x;

    int bid = blockIdx.x;
    int i = 0, rem = bid;
    while (rem >= C - 1 - i) { rem -= C - 1 - i; i++; }
    int j = i + 1 + rem;

    float ni = (float)g_counts[i], nj = (float)g_counts[j];
    float pc = ni + nj;
    float d2 = pc - 2.f;
    if (d2 == 0.f) d2 = 1e-5f;
    float b = d2 * 0.5f;

    float sxi = 0.f, qqi = 0.f, sxj = 0.f, qqj = 0.f;
#pragma unroll
    for (int g = 0; g < GRPS; g++) {
        float2 vi = g_pA[g * (C * D) + i * D + t];
        float2 vj = g_pA[g * (C * D) + j * D + t];
        sxi += vi.x; qqi += vi.y;
        sxj += vj.x; qqj += vj.y;
    }
    float mi = sxi / ni;
    float wi = qqi - sxi * mi;
    float mj = sxj / nj;
    float wj = qqj - sxj * mj;

    float hd   = (mi - mj) * 0.5f;
    float betw = hd * hd * pc;
    float x = betw / (betw + wi + wj);
    x = fminf(fmaxf(x, 1e-37f), 1.f - 1e-5f);

    // hybrid bitonic sort, descending; thread t ends holding sorted[t]
    float v = x;
#pragma unroll
    for (int k = 2; k <= D; k <<= 1) {
#pragma unroll
        for (int jj = k >> 1; jj > 0; jj >>= 1) {
            bool keepMax = (((t & k) == 0) == ((t & jj) == 0));
            float pv;
            if (jj >= 32) {
                sx[t] = v;
                __syncthreads();
                pv = sx[t ^ jj];
                __syncthreads();
            } else {
                pv = __shfl_xor_sync(0xffffffffu, v, jj);
            }
            v = keepMax ? fmaxf(v, pv) : fminf(v, pv);
        }
    }

    int K = 64;
    if (dptr) {
        int kv = dptr[0];
        if (kv >= 1 && kv <= D) K = kv;
    }

    float val = 0.f;
    if (t < K) {
        float s2 = -b * log1pf(-v);                // s = -b ln(1-x)
        float rs = sqrtf(s2);
        const float inv_sqrtpi = 0.5641895835477563f;  // 1/sqrt(pi)
        float I = erff(rs) - rs * expf(-s2) * (inv_sqrtpi * 0.25f / b);
        I = fminf(fmaxf(I, 1e-38f), 1.f);
        val = logf(I);
    }
    sred[t] = val;
    __syncthreads();
    for (int s = D / 2; s > 0; s >>= 1) {
        if (t < s) sred[t] += sred[t + s];
        __syncthreads();
    }
    if (t == 0) g_pairsum[bid] = (double)sred[0];
}

// ---------------- launch 5: final scalar reduce -----------------------------
__global__ void k_final(float* out) {
    __shared__ double sr[128];
    int t = threadIdx.x;
    sr[t] = (t < NPAIRS) ? g_pairsum[t] : 0.0;
    __syncthreads();
    for (int s = 64; s > 0; s >>= 1) {
        if (t < s) sr[t] += sr[t + s];
        __syncthreads();
    }
    if (t == 0) out[0] = (float)(-sr[0]);
}

// ---------------- launch ----------------
extern "C" void kernel_launch(void* const* d_in, const int* in_sizes, int n_in,
                              void* d_out, int out_size) {
    const float* hidden = (const float*)d_in[0];
    const int*   ids32  = (const int*)d_in[1];
    const int*   dptr   = (n_in > 2) ? (const int*)d_in[2] : nullptr;

    int N = in_sizes[0] / D;            // 65536

    k_order <<<NCHUNK, 256>>>(ids32, N);                 // launch 1
    k_pass1 <<<PBLK, 128>>>(hidden);                     // launch 2
    k_pass2a<<<(GRPS * C * D) / 256, 256>>>();           // launch 3
    k_pairs <<<NPAIRS, D>>>(dptr);                       // launch 4 (profiled)
    k_final <<<1, 128>>>((float*)d_out);                 // launch 5
}

// round 17
// speedup vs baseline: 1.3907x; 1.0842x over previous
#include <cuda_runtime.h>
#include <math.h>
#include <stdint.h>

#define C 16
#define D 512
#define CHUNK_ROWS 256
#define DPQ 128            // dims per quarter-block in pass 1
#define NPAIRS (C*(C-1)/2)
#define NCHUNK 256         // row chunks (N=65536 / 256)
#define PBLK (NCHUNK*4)    // pass-1 blocks = 1024 (4 dim-quarters)
#define GRPS 8             // stage-A groups
#define CPG (NCHUNK/GRPS)  // chunks per group = 32
#define FXSCALE 4294967296.0   // 2^32 fixed-point scale

// ---------------- device scratch (no allocations allowed) ----------------
__device__ float2 g_partial[PBLK * C * DPQ];        // 16 MB
__device__ float2 g_pA[GRPS * C * D];               // 512 KB (L2-resident)
__device__ int    g_chunkhist[NCHUNK * C];          // per-chunk class histogram
__device__ unsigned long long g_acc;                // fixed-point total
__device__ int    g_done;                           // pairs completion counter

__device__ __forceinline__ int get_id(const int* ids32, int i, int is64) {
    return is64 ? ids32[2 * i] : ids32[i];    // little-endian low word
}

// ---------------- launch 1: pass 1 with in-SMEM class-sorted order ---------
// block = (chunk of 256 rows) x (quarter of 512 dims), 128 threads.
// Each block: parallel dtype detect, deterministic 8-virtual-warp match_any
// ordering of its 256 rows (SMEM only), then sorted-order register-accum
// streaming with 8-wide batched loads. Quarter 0 publishes chunk histogram.
#define P1STEP(pp, vv)                                              \
    {                                                               \
        int cc = (pp) >> 16;                                        \
        if (cc != cur) {                                            \
            out[cur * DPQ] = make_float2(s, q);                     \
            s = 0.f; q = 0.f; cur = cc;                             \
        }                                                           \
        s += (vv); q = fmaf((vv), (vv), q);                         \
    }

__global__ __launch_bounds__(128) void k_pass1(const float* __restrict__ hidden,
                                               const int* __restrict__ ids32,
                                               int n) {
    __shared__ int s_whist[8][C];
    __shared__ int s_wbase[8][C];
    __shared__ int s_hist[C];
    __shared__ int s_off[17];
    __shared__ int s_ord[CHUNK_ROWS];
    __shared__ int s_any;
    int t = threadIdx.x;
    int w = t >> 5, lane = t & 31;
    unsigned lmask = (1u << lane) - 1u;
    int quarter = blockIdx.x & 3;
    int chunk   = blockIdx.x >> 2;
    int rowBase = chunk * CHUNK_ROWS;

    if (t == 0) {
        s_any = 0;
        if (blockIdx.x == 0) { g_acc = 0ull; g_done = 0; }
    }
    if (t < 128) ((int*)s_whist)[t] = 0;
    __syncthreads();
    // parallel dtype detect: int64 ids < C have zero high words
    int lim = n / 2; if (lim > 64) lim = 64;
    if (t < lim && ids32[2 * t + 1] != 0) atomicOr(&s_any, 1);
    __syncthreads();
    int is64 = (s_any == 0);

    int cA = get_id(ids32, rowBase + t, is64) & (C - 1);
    int cB = get_id(ids32, rowBase + t + 128, is64) & (C - 1);

    unsigned mA = __match_any_sync(0xffffffffu, cA);
    int rA = __popc(mA & lmask);
    if (rA == 0) s_whist[w][cA] = __popc(mA);
    unsigned mB = __match_any_sync(0xffffffffu, cB);
    int rB = __popc(mB & lmask);
    if (rB == 0) s_whist[w + 4][cB] = __popc(mB);
    __syncthreads();

    if (t < C) {
        int acc = 0;
#pragma unroll
        for (int vw = 0; vw < 8; vw++) { s_wbase[vw][t] = acc; acc += s_whist[vw][t]; }
        s_hist[t] = acc;
    }
    __syncthreads();
    if (t == 0) {
        int acc = 0;
#pragma unroll
        for (int cc = 0; cc < C; cc++) { s_off[cc] = acc; acc += s_hist[cc]; }
        s_off[C] = acc;
    }
    __syncthreads();

    s_ord[s_off[cA] + s_wbase[w][cA] + rA]     = t | (cA << 16);
    s_ord[s_off[cB] + s_wbase[w + 4][cB] + rB] = (t + 128) | (cB << 16);
    if (quarter == 0 && t < C) g_chunkhist[chunk * C + t] = s_hist[t];
    __syncthreads();

    const float* base = hidden + (size_t)rowBase * D + quarter * DPQ + t;
    float2*      out  = g_partial + (size_t)blockIdx.x * (C * DPQ) + t;

    float s = 0.f, q = 0.f;
    int cur = s_ord[0] >> 16;
#pragma unroll 1
    for (int k = 0; k < CHUNK_ROWS; k += 8) {
        int p0 = s_ord[k + 0], p1 = s_ord[k + 1], p2 = s_ord[k + 2], p3 = s_ord[k + 3];
        int p4 = s_ord[k + 4], p5 = s_ord[k + 5], p6 = s_ord[k + 6], p7 = s_ord[k + 7];
        float v0 = base[(size_t)(p0 & 0xffff) * D];
        float v1 = base[(size_t)(p1 & 0xffff) * D];
        float v2 = base[(size_t)(p2 & 0xffff) * D];
        float v3 = base[(size_t)(p3 & 0xffff) * D];
        float v4 = base[(size_t)(p4 & 0xffff) * D];
        float v5 = base[(size_t)(p5 & 0xffff) * D];
        float v6 = base[(size_t)(p6 & 0xffff) * D];
        float v7 = base[(size_t)(p7 & 0xffff) * D];
        P1STEP(p0, v0) P1STEP(p1, v1) P1STEP(p2, v2) P1STEP(p3, v3)
        P1STEP(p4, v4) P1STEP(p5, v5) P1STEP(p6, v6) P1STEP(p7, v7)
    }
    out[cur * DPQ] = make_float2(s, q);
#pragma unroll
    for (int cc = 0; cc < C; cc++)
        if (s_off[cc + 1] == s_off[cc]) out[cc * DPQ] = make_float2(0.f, 0.f);
}

// ---------------- launch 2: pass 2 stage A (wide coalesced) ----------------
__global__ __launch_bounds__(256) void k_pass2a() {
    int gid  = blockIdx.x * 256 + threadIdx.x;     // 0 .. 65535
    int item = gid & (C * D - 1);                  // 0 .. 8191
    int grp  = gid >> 13;                          // 0 .. 7
    int c    = item >> 9;
    int dim  = item & (D - 1);
    int quarter = dim >> 7;
    int tq      = dim & (DPQ - 1);
    const float2* p = g_partial + (size_t)c * DPQ + tq;
    float sx = 0.f, qq = 0.f;
#pragma unroll 8
    for (int k = 0; k < CPG; k++) {
        int chunk = grp * CPG + k;                 // 0 .. 255
        int blk   = (chunk << 2) | quarter;        // 0 .. 1023
        float2 v = p[(size_t)blk * (C * DPQ)];
        sx += v.x; qq += v.y;
    }
    g_pA[grp * (C * D) + item] = make_float2(sx, qq);
}

// ---------------- launch 3: pair kernel + counts + final --------------------
// Counts reduced from chunk histograms (fixed tree). fp32 stats from the
// 512 KB L2-resident g_pA; hybrid shfl/smem bitonic sort; large-b asymptotic
// log-betainc; per-pair sum -> deterministic 2^32 fixed-point atomicAdd;
// last block writes the scalar.
__global__ __launch_bounds__(D) void k_pairs(const int* __restrict__ dptr,
                                             float* __restrict__ outp) {
    __shared__ float sx[D];
    __shared__ float sred[D];
    __shared__ int   s_c[2 * NCHUNK];
    int t = threadIdx.x;

    int bid = blockIdx.x;
    int i = 0, rem = bid;
    while (rem >= C - 1 - i) { rem -= C - 1 - i; i++; }
    int j = i + 1 + rem;

    // counts for classes i and j (deterministic tree reduce)
    s_c[t] = (t < NCHUNK) ? g_chunkhist[t * C + i]
                          : g_chunkhist[(t - NCHUNK) * C + j];
    __syncthreads();
    for (int s = NCHUNK / 2; s > 0; s >>= 1) {
        if (t < s) s_c[t] += s_c[t + s];
        else if (t >= NCHUNK && t < NCHUNK + s) s_c[t] += s_c[t + s];
        __syncthreads();
    }
    float ni = (float)s_c[0], nj = (float)s_c[NCHUNK];

    float pc = ni + nj;
    float d2 = pc - 2.f;
    if (d2 == 0.f) d2 = 1e-5f;
    float b = d2 * 0.5f;

    float sxi = 0.f, qqi = 0.f, sxj = 0.f, qqj = 0.f;
#pragma unroll
    for (int g = 0; g < GRPS; g++) {
        float2 vi = g_pA[g * (C * D) + i * D + t];
        float2 vj = g_pA[g * (C * D) + j * D + t];
        sxi += vi.x; qqi += vi.y;
        sxj += vj.x; qqj += vj.y;
    }
    float mi = sxi / ni;
    float wi = qqi - sxi * mi;
    float mj = sxj / nj;
    float wj = qqj - sxj * mj;

    float hd   = (mi - mj) * 0.5f;
    float betw = hd * hd * pc;
    float x = betw / (betw + wi + wj);
    x = fminf(fmaxf(x, 1e-37f), 1.f - 1e-5f);

    // hybrid bitonic sort, descending; thread t ends holding sorted[t]
    float v = x;
#pragma unroll
    for (int k = 2; k <= D; k <<= 1) {
#pragma unroll
        for (int jj = k >> 1; jj > 0; jj >>= 1) {
            bool keepMax = (((t & k) == 0) == ((t & jj) == 0));
            float pv;
            if (jj >= 32) {
                sx[t] = v;
                __syncthreads();
                pv = sx[t ^ jj];
                __syncthreads();
            } else {
                pv = __shfl_xor_sync(0xffffffffu, v, jj);
            }
            v = keepMax ? fmaxf(v, pv) : fminf(v, pv);
        }
    }

    int K = 64;
    if (dptr) {
        int kv = dptr[0];
        if (kv >= 1 && kv <= D) K = kv;
    }

    float val = 0.f;
    if (t < K) {
        float s2 = -b * log1pf(-v);                // s = -b ln(1-x)
        float rs = sqrtf(s2);
        const float inv_sqrtpi = 0.5641895835477563f;  // 1/sqrt(pi)
        float I = erff(rs) - rs * expf(-s2) * (inv_sqrtpi * 0.25f / b);
        I = fminf(fmaxf(I, 1e-38f), 1.f);
        val = logf(I);
    }
    sred[t] = val;
    __syncthreads();
    for (int s = D / 2; s > 0; s >>= 1) {
        if (t < s) sred[t] += sred[t + s];
        __syncthreads();
    }

    if (t == 0) {
        long long qv = llrint((double)sred[0] * FXSCALE);
        atomicAdd(&g_acc, (unsigned long long)qv);
        __threadfence();
        int done = atomicAdd(&g_done, 1);
        if (done == NPAIRS - 1) {
            unsigned long long tot = atomicAdd(&g_acc, 0ull);
            outp[0] = (float)(-(double)(long long)tot / FXSCALE);
        }
    }
}

// ---------------- launch ----------------
extern "C" void kernel_launch(void* const* d_in, const int* in_sizes, int n_in,
                              void* d_out, int out_size) {
    const float* hidden = (const float*)d_in[0];
    const int*   ids32  = (const int*)d_in[1];
    const int*   dptr   = (n_in > 2) ? (const int*)d_in[2] : nullptr;

    int N = in_sizes[0] / D;            // 65536

    k_pass1 <<<PBLK, 128>>>(hidden, ids32, N);           // launch 1
    k_pass2a<<<(GRPS * C * D) / 256, 256>>>();           // launch 2
    k_pairs <<<NPAIRS, D>>>(dptr, (float*)d_out);        // launch 3 (profiled slot rotates)
}